// round 1
// baseline (speedup 1.0000x reference)
#include <cuda_runtime.h>
#include <cuda_bf16.h>

// FlowCPAB: integrate piecewise-affine ODE (CPAB) for 16.7M points, nc=5 cells,
// nc+2 = 7 scan steps. A = (B @ theta).reshape(5,2) gives per-cell (a,b).
// Outputs: z -> out[0:N], logder -> out[N:2N].

#define NC 5
#define EPSC 1e-7f
#define TINY 1e-12f
#define BIGV 1e10f

__global__ void __launch_bounds__(256)
flowcpab_kernel(const float* __restrict__ x,
                const float* __restrict__ theta,
                const float* __restrict__ Bm,
                float* __restrict__ out, int n)
{
    // Per-cell constants, computed once per block (10 dot products of length 6).
    __shared__ float s_a[NC], s_b[NC], s_boa[NC], s_isa[NC], s_isb[NC];
    const int tid = threadIdx.x;
    if (tid < NC) {
        float a = 0.f, b = 0.f;
#pragma unroll
        for (int k = 0; k < 6; ++k) {
            a += Bm[(2 * tid) * 6 + k] * theta[k];
            b += Bm[(2 * tid + 1) * 6 + k] * theta[k];
        }
        const bool big = fabsf(a) > 1e-8f;
        const float sa = big ? a : 1.0f;
        const float sb = (fabsf(b) > TINY) ? b : TINY;
        s_a[tid]   = a;
        s_b[tid]   = b;
        s_boa[tid] = b / sa;      // exact divisions, once per block
        s_isa[tid] = 1.0f / sa;
        s_isb[tid] = 1.0f / sb;
    }
    __syncthreads();

    const int i  = blockIdx.x * blockDim.x + tid;
    const int ii = (i < n) ? i : (n - 1);   // keep all lanes live for __all_sync

    float xc = x[ii];
    xc = fminf(fmaxf(xc, EPSC), 1.0f - EPSC);
    int c = (int)floorf(xc * (float)NC);
    c = max(0, min(c, NC - 1));

    float t = 1.0f;
    float logder = 0.0f;

#pragma unroll 1
    for (int it = 0; it < NC + 2; ++it) {
        const float a   = s_a[c];
        const float b   = s_b[c];
        const float boa = s_boa[c];
        const float isa = s_isa[c];
        const float isb = s_isb[c];

        const float v   = fmaf(a, xc, b);
        const bool  big = fabsf(a) > 1e-8f;

        // psi(t): state after flowing remaining time t inside current cell
        const float eat = __expf(a * t);
        const float psi = big ? fmaf(xc, eat, boa * (eat - 1.0f))
                              : fmaf(b, t, xc);

        const bool  right = (v >= 0.0f);
        const float xb    = (float)(right ? (c + 1) : c) * (1.0f / (float)NC);

        // time to hit cell boundary
        const float den   = xc + boa;
        const float sden  = (fabsf(den) > TINY) ? den : TINY;
        const float ratio = __fdividef(xb + boa, sden);
        float thit = big ? (__logf(fmaxf(ratio, TINY)) * isa)
                         : ((xb - xc) * isb);

        const bool valid = (fabsf(v) > TINY) && (thit >= 0.0f) &&
                           (!big || (ratio > 0.0f));
        if (!valid) thit = BIGV;

        const bool  hits = (thit < t);
        const float dt   = hits ? thit : t;

        xc = hits ? xb : psi;
        if (hits) c = max(0, min(c + (right ? 1 : -1), NC - 1));
        logder = fmaf(a, dt, logder);
        t -= dt;

        // once t == 0 the state is an exact fixed point of the step; reference
        // keeps iterating with zero effect — we can stop when the whole warp is done.
        if (__all_sync(0xFFFFFFFFu, t <= 0.0f)) break;
    }

    if (i < n) {
        out[i]     = xc;
        out[n + i] = logder;
    }
}

extern "C" void kernel_launch(void* const* d_in, const int* in_sizes, int n_in,
                              void* d_out, int out_size)
{
    const float* x     = (const float*)d_in[0];
    const float* theta = (const float*)d_in[1];
    const float* Bm    = (const float*)d_in[2];
    float* out = (float*)d_out;
    const int n = in_sizes[0];

    const int threads = 256;
    const int blocks  = (n + threads - 1) / threads;
    flowcpab_kernel<<<blocks, threads>>>(x, theta, Bm, out, n);
}

// round 2
// speedup vs baseline: 2.3141x; 2.3141x over previous
#include <cuda_runtime.h>
#include <cuda_bf16.h>

// FlowCPAB analytic-chain version.
// Step 1 per point follows the reference formula exactly (v, psi, thit, valid).
// If the point crosses a boundary, the rest of the trajectory depends only on
// (boundary index, direction, remaining time): continuity of the piecewise-affine
// field means sign(v) is invariant along a flow, and cell-traversal times from
// boundaries are fixed. Precomputed cumulative tables give the final cell and
// logder with 5 branch-free compares + one final psi. Absorption at x=0/1
// reproduces the reference's clamped sticking (dt=0 thereafter).

#define NC 5
#define EPSC 1e-7f
#define TINY 1e-12f
#define BIGV 1e10f

__device__ __forceinline__ void flow_point(
    float x, float& zo, float& lo,
    const float* __restrict__ s_a,  const float* __restrict__ s_b,
    const float* __restrict__ s_boa,const float* __restrict__ s_isa,
    const float* __restrict__ s_isb,const float* __restrict__ s_bt,
    const float* __restrict__ s_TR, const float* __restrict__ s_TL,
    const float* __restrict__ s_LR, const float* __restrict__ s_LL)
{
    x = fminf(fmaxf(x, EPSC), 1.0f - EPSC);
    int c = min(NC - 1, (int)(x * (float)NC));

    const float a   = s_a[c];
    const float b   = s_b[c];
    const float boa = s_boa[c];
    const float v   = fmaf(a, x, b);
    const bool  big = fabsf(a) > 1e-8f;
    const bool  right = (v >= 0.0f);
    const int   jb  = right ? (c + 1) : c;
    const float xb  = s_bt[jb];

    const float den   = x + boa;
    const float sden  = (fabsf(den) > TINY) ? den : TINY;
    const float ratio = __fdividef(xb + boa, sden);
    float thit = big ? (__logf(fmaxf(ratio, TINY)) * s_isa[c])
                     : ((xb - x) * s_isb[c]);
    const bool valid = (fabsf(v) > TINY) && (thit >= 0.0f) &&
                       (!big || (ratio > 0.0f));
    if (!valid) thit = BIGV;

    if (!(thit < 1.0f)) {
        // never leaves the starting cell: psi(t=1)
        const float eat = __expf(a);
        zo = big ? fmaf(x, eat, boa * (eat - 1.0f)) : (x + b);
        lo = a;
        return;
    }

    float s  = 1.0f - thit;
    float ld = a * thit;

    const float* Tc = right ? s_TR : s_TL;
    const float* Lc = right ? s_LR : s_LL;
    const int base = jb * 6;
    int mm = 0;
#pragma unroll
    for (int m = 1; m <= 5; ++m) mm += (Tc[base + m] < s) ? 1 : 0;

    ld += Lc[base + mm];
    const float srem = s - Tc[base + mm];
    const int jb2 = right ? (jb + mm) : (jb - mm);

    if (right ? (jb2 == NC) : (jb2 == 0)) {      // absorbed at 1.0 / 0.0
        zo = right ? 1.0f : 0.0f;
        lo = ld;
        return;
    }

    const int   cc  = right ? jb2 : (jb2 - 1);
    const float x0  = s_bt[jb2];
    const float a2  = s_a[cc];
    const bool  big2 = fabsf(a2) > 1e-8f;
    const float eat = __expf(a2 * srem);
    zo = big2 ? fmaf(x0, eat, s_boa[cc] * (eat - 1.0f))
              : fmaf(s_b[cc], srem, x0);
    lo = ld + a2 * srem;
}

__global__ void __launch_bounds__(256)
flowcpab_kernel(const float* __restrict__ x,
                const float* __restrict__ theta,
                const float* __restrict__ Bm,
                float* __restrict__ out, int n)
{
    __shared__ float s_a[NC], s_b[NC], s_boa[NC], s_isa[NC], s_isb[NC];
    __shared__ float s_tauR[NC], s_tauL[NC], s_ldRc[NC], s_ldLc[NC];
    __shared__ float s_bt[NC + 1];
    __shared__ float s_TR[36], s_TL[36], s_LR[36], s_LL[36];

    const int tid = threadIdx.x;
    if (tid <= NC) s_bt[tid] = (float)tid / (float)NC;
    if (tid < NC) {
        float a = 0.f, b = 0.f;
#pragma unroll
        for (int k = 0; k < 6; ++k) {
            a += Bm[(2 * tid) * 6 + k]     * theta[k];
            b += Bm[(2 * tid + 1) * 6 + k] * theta[k];
        }
        const bool  big = fabsf(a) > 1e-8f;
        const float sa  = big ? a : 1.0f;
        const float sb  = (fabsf(b) > TINY) ? b : TINY;
        const float boa = b / sa;
        s_a[tid] = a; s_b[tid] = b; s_boa[tid] = boa;
        s_isa[tid] = 1.0f / sa; s_isb[tid] = 1.0f / sb;

        const float xl = (float)tid / (float)NC;
        const float xr = (float)(tid + 1) / (float)NC;
        {   // rightward traversal of cell tid (enter xl, exit xr)
            const float v = a * xl + b;
            const float den = xl + boa;
            const float sden = (fabsf(den) > TINY) ? den : TINY;
            const float ratio = (xr + boa) / sden;
            const float th = big ? (logf(fmaxf(ratio, TINY)) / sa)
                                 : ((xr - xl) / sb);
            const bool valid = (fabsf(v) > TINY) && (th >= 0.f) &&
                               (!big || ratio > 0.f);
            const float tau = valid ? th : BIGV;
            s_tauR[tid] = tau;
            s_ldRc[tid] = a * tau;
        }
        {   // leftward traversal of cell tid (enter xr, exit xl)
            const float v = a * xr + b;
            const float den = xr + boa;
            const float sden = (fabsf(den) > TINY) ? den : TINY;
            const float ratio = (xl + boa) / sden;
            const float th = big ? (logf(fmaxf(ratio, TINY)) / sa)
                                 : ((xl - xr) / sb);
            const bool valid = (fabsf(v) > TINY) && (th >= 0.f) &&
                               (!big || ratio > 0.f);
            const float tau = valid ? th : BIGV;
            s_tauL[tid] = tau;
            s_ldLc[tid] = a * tau;
        }
    }
    __syncthreads();
    if (tid < 6) {
        const int j = tid;
        float tc = 0.f, lc = 0.f;
        s_TR[j * 6] = 0.f; s_LR[j * 6] = 0.f;
        for (int m = 1; m <= 5; ++m) {
            const int cell = j + m - 1;
            if (cell <= NC - 1) { tc += s_tauR[cell]; lc += s_ldRc[cell]; }
            else                { tc = BIGV; }
            s_TR[j * 6 + m] = tc; s_LR[j * 6 + m] = lc;
        }
        tc = 0.f; lc = 0.f;
        s_TL[j * 6] = 0.f; s_LL[j * 6] = 0.f;
        for (int m = 1; m <= 5; ++m) {
            const int cell = j - m;
            if (cell >= 0) { tc += s_tauL[cell]; lc += s_ldLc[cell]; }
            else           { tc = BIGV; }
            s_TL[j * 6 + m] = tc; s_LL[j * 6 + m] = lc;
        }
    }
    __syncthreads();

    const int stride = gridDim.x * blockDim.x;

    if ((n & 3) == 0) {
        const int n4 = n >> 2;
        const float4* __restrict__ x4 = (const float4*)x;
        float4* __restrict__ z4 = (float4*)out;
        float4* __restrict__ l4 = (float4*)(out + n);
        for (int i = blockIdx.x * blockDim.x + tid; i < n4; i += stride) {
            const float4 xv = x4[i];
            float4 zv, lv;
            flow_point(xv.x, zv.x, lv.x, s_a, s_b, s_boa, s_isa, s_isb, s_bt, s_TR, s_TL, s_LR, s_LL);
            flow_point(xv.y, zv.y, lv.y, s_a, s_b, s_boa, s_isa, s_isb, s_bt, s_TR, s_TL, s_LR, s_LL);
            flow_point(xv.z, zv.z, lv.z, s_a, s_b, s_boa, s_isa, s_isb, s_bt, s_TR, s_TL, s_LR, s_LL);
            flow_point(xv.w, zv.w, lv.w, s_a, s_b, s_boa, s_isa, s_isb, s_bt, s_TR, s_TL, s_LR, s_LL);
            z4[i] = zv;
            l4[i] = lv;
        }
    } else {
        for (int i = blockIdx.x * blockDim.x + tid; i < n; i += stride) {
            float zz, ll;
            flow_point(x[i], zz, ll, s_a, s_b, s_boa, s_isa, s_isb, s_bt, s_TR, s_TL, s_LR, s_LL);
            out[i] = zz;
            out[n + i] = ll;
        }
    }
}

extern "C" void kernel_launch(void* const* d_in, const int* in_sizes, int n_in,
                              void* d_out, int out_size)
{
    const float* x     = (const float*)d_in[0];
    const float* theta = (const float*)d_in[1];
    const float* Bm    = (const float*)d_in[2];
    float* out = (float*)d_out;
    const int n = in_sizes[0];

    const int threads = 256;
    int work_items = ((n & 3) == 0) ? (n >> 2) : n;
    int blocks = (work_items + threads - 1) / threads;
    if (blocks > 4096) blocks = 4096;
    if (blocks < 1) blocks = 1;
    flowcpab_kernel<<<blocks, threads>>>(x, theta, Bm, out, n);
}

// round 3
// speedup vs baseline: 2.4456x; 1.0568x over previous
#include <cuda_runtime.h>
#include <cuda_bf16.h>

// FlowCPAB closed-form-per-segment version.
// setup_kernel (1 block) precomputes, per starting cell, x-thresholds and
// per-segment coefficients such that for x in segment:
//   u  = flag ? log|x + C0| : x
//   z  = C1 * exp(G*u) + C4*u + C2
//   ld = D1*u + D2
// This is exact CPAB algebra: thit = P - Q*u, srem = S0 + Q*u, and the final
// psi/absorption all reduce to this form. Segment boundaries are continuity
// points of (z, logder) so threshold rounding is harmless.

#define NC 5
#define EPSC 1e-7f

__device__ float d_thr[NC * 9];        // 8 thresholds/cell, stride 9
__device__ float d_cf[NC * 9 * 9];     // 45 segments x {C0,FL,G,C1,C4,C2,D1,D2,pad}

__global__ void setup_kernel(const float* __restrict__ theta,
                             const float* __restrict__ Bm)
{
    const int tid = threadIdx.x;
    __shared__ double A[5], Bc[5], BOA[5], SBv[5];
    __shared__ int    BIGF[5];
    __shared__ double TAUR[5], TAUL[5], LDRv[5], LDLv[5];
    __shared__ double TR[6][6], TLm[6][6], LRm[6][6], LLm[6][6];
    __shared__ double THR[5][8];
    __shared__ int    NT[5];

    if (tid < 5) {
        double a = 0.0, b = 0.0;
        for (int k = 0; k < 6; ++k) {
            a += (double)Bm[(2 * tid) * 6 + k]     * (double)theta[k];
            b += (double)Bm[(2 * tid + 1) * 6 + k] * (double)theta[k];
        }
        A[tid] = a; Bc[tid] = b;
        const int big = fabs(a) > 1e-8;
        BIGF[tid] = big;
        const double sa  = big ? a : 1.0;
        const double sb  = (fabs(b) > 1e-12) ? b : 1e-12;
        const double boa = b / sa;
        SBv[tid] = sb; BOA[tid] = boa;
        const double xl = tid / 5.0, xr = (tid + 1) / 5.0;
        {   // rightward traversal of this cell
            const double v = a * xl + b, den = xl + boa;
            const double sden = (fabs(den) > 1e-12) ? den : 1e-12;
            const double ratio = (xr + boa) / sden;
            const double th = big ? log(fmax(ratio, 1e-12)) / sa : (xr - xl) / sb;
            const int valid = (fabs(v) > 1e-12) && (th >= 0.0) && (!big || ratio > 0.0);
            TAUR[tid] = valid ? th : 1e10;
            LDRv[tid] = valid ? a * th : 0.0;
        }
        {   // leftward traversal
            const double v = a * xr + b, den = xr + boa;
            const double sden = (fabs(den) > 1e-12) ? den : 1e-12;
            const double ratio = (xl + boa) / sden;
            const double th = big ? log(fmax(ratio, 1e-12)) / sa : (xl - xr) / sb;
            const int valid = (fabs(v) > 1e-12) && (th >= 0.0) && (!big || ratio > 0.0);
            TAUL[tid] = valid ? th : 1e10;
            LDLv[tid] = valid ? a * th : 0.0;
        }
    }
    __syncthreads();
    if (tid < 12) {                      // cumulative chain tables per boundary
        const int j = tid % 6, dir = tid / 6;
        double tc = 0.0, lc = 0.0;
        if (dir == 0) {
            TR[j][0] = 0.0; LRm[j][0] = 0.0;
            for (int m = 1; m <= 5; ++m) {
                const int cell = j + m - 1;
                if (cell <= 4 && tc < 1e9 && TAUR[cell] < 1e9) { tc += TAUR[cell]; lc += LDRv[cell]; }
                else tc = 1e10;
                TR[j][m] = tc; LRm[j][m] = lc;
            }
        } else {
            TLm[j][0] = 0.0; LLm[j][0] = 0.0;
            for (int m = 1; m <= 5; ++m) {
                const int cell = j - m;
                if (cell >= 0 && tc < 1e9 && TAUL[cell] < 1e9) { tc += TAUL[cell]; lc += LDLv[cell]; }
                else tc = 1e10;
                TLm[j][m] = tc; LLm[j][m] = lc;
            }
        }
    }
    __syncthreads();
    if (tid < 5) {                       // per-cell thresholds
        const int c = tid;
        const double a = A[c], b = Bc[c], boa = BOA[c], sb = SBv[c];
        const int big = BIGF[c];
        const double xl = c / 5.0, xr = (c + 1) / 5.0;
        double cand[16]; int ncand = 0;
        if (big) {
            const double xs = -boa;      // direction switch v=0
            if (xs > xl && xs < xr) cand[ncand++] = xs;
        }
        for (int dir = 0; dir < 2; ++dir) {
            const int jb = (dir == 0) ? c + 1 : c;
            const double xb = jb / 5.0;
            const double* Tc = (dir == 0) ? TR[jb] : TLm[jb];
            for (int m = 0; m <= 5; ++m) {
                const double th = (m == 0) ? 1.0 : (1.0 - Tc[m]);  // thit = th threshold
                if (!(th > 0.0 && th <= 1.0)) continue;
                const double xt = big ? (xb + boa) * exp(-a * th) - boa
                                      : xb - sb * th;
                if (xt > xl && xt < xr) {
                    const double v = a * xt + b;
                    const int r = (v >= 0.0);
                    if ((r && dir == 0) || (!r && dir == 1))     // direction must match
                        if (ncand < 16) cand[ncand++] = xt;
                }
            }
        }
        for (int i = 1; i < ncand; ++i) {                         // insertion sort
            double v = cand[i]; int j = i - 1;
            while (j >= 0 && cand[j] > v) { cand[j + 1] = cand[j]; --j; }
            cand[j + 1] = v;
        }
        int nt = 0;
        for (int i = 0; i < ncand && nt < 8; ++i)
            if (nt == 0 || cand[i] - THR[c][nt - 1] > 1e-13) { THR[c][nt] = cand[i]; ++nt; }
        NT[c] = nt;
        for (int k = 0; k < 8; ++k)
            d_thr[c * 9 + k] = (k < nt) ? (float)THR[c][k] : 1e30f;
    }
    __syncthreads();
    if (tid < 45) {                      // per-segment coefficients
        const int c = tid / 9, sgi = tid % 9;
        const int nt = NT[c];
        if (sgi <= nt) {
            const double xl = c / 5.0, xr = (c + 1) / 5.0;
            const double lo = (sgi == 0) ? xl : THR[c][sgi - 1];
            const double hi = (sgi == nt) ? xr : THR[c][sgi];
            const double xm = 0.5 * (lo + hi);
            const double a = A[c], b = Bc[c], boa = BOA[c], sb = SBv[c];
            const int big = BIGF[c];
            double C0 = 0, FL = 0, G = 0, C1 = 0, C4 = 0, C2 = 0, D1 = 0, D2 = 0;
            const double v = a * xm + b;
            const double den = xm + boa;
            const double sden = (fabs(den) > 1e-12) ? den : 1e-12;
            const int right = (v >= 0.0);
            const int jb = right ? c + 1 : c;
            const double xb = jb / 5.0;
            const double ratio = (xb + boa) / sden;
            const double thit = big ? log(fmax(ratio, 1e-12)) / a : (xb - xm) / sb;
            const int valid = (fabs(v) > 1e-12) && (thit >= 0.0) && (!big || ratio > 0.0);
            if (!valid || thit >= 1.0) {
                // never leaves cell: psi(1) (linear in x)
                if (big) { const double ea = exp(a); C4 = ea; C2 = boa * (ea - 1.0); }
                else     { C4 = 1.0; C2 = b; }
                D2 = a;
            } else {
                const double s = 1.0 - thit;
                const double* Tc = right ? TR[jb] : TLm[jb];
                const double* Lc = right ? LRm[jb] : LLm[jb];
                int mm = 0;
                for (int m = 1; m <= 5; ++m) mm += (Tc[m] < s) ? 1 : 0;
                const double Lcum = Lc[mm], Tmm = Tc[mm];
                const int jb2 = right ? jb + mm : jb - mm;
                double P, Q;
                if (big) { FL = 1.0; C0 = boa; const double LB = log(fabs(xb + boa)); P = LB / a; Q = 1.0 / a; }
                else     { FL = 0.0; C0 = 0.0; P = xb / sb; Q = 1.0 / sb; }
                const double S0 = 1.0 - Tmm - P;      // srem = S0 + Q*u
                const int absorbed = right ? (jb2 == 5) : (jb2 == 0);
                if (absorbed) {
                    C2 = right ? 1.0 : 0.0;
                    D1 = -a * Q; D2 = a * P + Lcum;
                } else {
                    const int cc = right ? jb2 : jb2 - 1;
                    const double x0 = jb2 / 5.0;
                    const double a2 = A[cc], b2 = Bc[cc];
                    if (fabs(a2) > 1e-8) {
                        const double boa2 = b2 / a2;
                        G = a2 * Q; C1 = (x0 + boa2) * exp(a2 * S0); C2 = -boa2;
                    } else {
                        C4 = b2 * Q; C2 = x0 + b2 * S0;
                    }
                    D1 = (a2 - a) * Q; D2 = a * P + Lcum + a2 * S0;
                }
            }
            float* cf = &d_cf[(c * 9 + sgi) * 9];
            cf[0] = (float)C0; cf[1] = (float)FL; cf[2] = (float)G; cf[3] = (float)C1;
            cf[4] = (float)C4; cf[5] = (float)C2; cf[6] = (float)D1; cf[7] = (float)D2;
        }
    }
}

__device__ __forceinline__ void eval_point(float x, float& z, float& ld,
                                           const float* __restrict__ s_thr,
                                           const float* __restrict__ s_cf)
{
    x = fminf(fmaxf(x, EPSC), 1.0f - EPSC);
    const int c = min(NC - 1, (int)(x * (float)NC));
    const float* th = s_thr + c * 9;
    int mm = 0;
#pragma unroll
    for (int k = 0; k < 8; ++k) mm += (th[k] < x) ? 1 : 0;
    const float* cf = s_cf + (c * 9 + mm) * 9;
    const float C0 = cf[0], FL = cf[1], G = cf[2], C1 = cf[3];
    const float C4 = cf[4], C2 = cf[5], D1 = cf[6], D2 = cf[7];
    const float t = x + C0;
    const float u = (FL != 0.0f) ? __logf(fabsf(t)) : x;
    const float e = __expf(G * u);
    z  = fmaf(C1, e, fmaf(C4, u, C2));
    ld = fmaf(D1, u, D2);
}

__global__ void __launch_bounds__(256)
flowcpab_main(const float* __restrict__ x, float* __restrict__ out, int n)
{
    __shared__ float s_thr[NC * 9];
    __shared__ float s_cf[NC * 9 * 9];
    const int tid = threadIdx.x;
    for (int i = tid; i < NC * 9; i += blockDim.x)       s_thr[i] = d_thr[i];
    for (int i = tid; i < NC * 9 * 9; i += blockDim.x)   s_cf[i]  = d_cf[i];
    __syncthreads();

    const int stride = gridDim.x * blockDim.x;

    if ((n & 3) == 0) {
        const int n4 = n >> 2;
        const float4* __restrict__ x4 = (const float4*)x;
        float4* __restrict__ z4 = (float4*)out;
        float4* __restrict__ l4 = (float4*)(out + n);
        for (int i = blockIdx.x * blockDim.x + tid; i < n4; i += stride) {
            const float4 xv = x4[i];
            float4 zv, lv;
            eval_point(xv.x, zv.x, lv.x, s_thr, s_cf);
            eval_point(xv.y, zv.y, lv.y, s_thr, s_cf);
            eval_point(xv.z, zv.z, lv.z, s_thr, s_cf);
            eval_point(xv.w, zv.w, lv.w, s_thr, s_cf);
            z4[i] = zv;
            l4[i] = lv;
        }
    } else {
        for (int i = blockIdx.x * blockDim.x + tid; i < n; i += stride) {
            float zz, ll;
            eval_point(x[i], zz, ll, s_thr, s_cf);
            out[i] = zz;
            out[n + i] = ll;
        }
    }
}

extern "C" void kernel_launch(void* const* d_in, const int* in_sizes, int n_in,
                              void* d_out, int out_size)
{
    const float* x     = (const float*)d_in[0];
    const float* theta = (const float*)d_in[1];
    const float* Bm    = (const float*)d_in[2];
    float* out = (float*)d_out;
    const int n = in_sizes[0];

    setup_kernel<<<1, 64>>>(theta, Bm);

    const int threads = 256;
    int work = ((n & 3) == 0) ? (n >> 2) : n;
    int blocks = (work + threads - 1) / threads;
    if (blocks > 4096) blocks = 4096;
    if (blocks < 1) blocks = 1;
    flowcpab_main<<<blocks, threads>>>(x, out, n);
}

// round 4
// speedup vs baseline: 3.6138x; 1.4777x over previous
#include <cuda_runtime.h>
#include <cuda_bf16.h>

// FlowCPAB closed-form-per-segment, bin-table edition.
// setup_kernel (1 block, fp32) precomputes per-cell thresholds and per-segment
// coefficients of the exact closed form
//   u  = FL ? log|x + C0| : x
//   z  = C1 * exp(G*u) + C4*u + C2
//   ld = D1*u + D2
// plus a 1280-bin uniform lookup table over [0,1): each bin holds
// {thr0, thr1, base_seg} so segment resolution is 1 LDS.128 + 2 compares.

#define NC 5
#define EPSC 1e-7f
#define NB 1280              // 5 * 256: bins never straddle cell boundaries
#define BPC 256              // bins per cell

__device__ float4 d_bin[NB];          // {thr0, thr1, base_as_float_bits, pad}
__device__ float4 d_cf[NC * 9 * 2];   // per segment: {C0,G,C1,C4},{C2,D1,D2,FL}

__global__ void setup_kernel(const float* __restrict__ theta,
                             const float* __restrict__ Bm)
{
    const int tid = threadIdx.x;
    __shared__ float A[5], Bc[5], BOA[5], SBv[5];
    __shared__ int   BIGF[5];
    __shared__ float TAUR[5], TAUL[5], LDRv[5], LDLv[5];
    __shared__ float TR[6][6], TLm[6][6], LRm[6][6], LLm[6][6];
    __shared__ float THR[5][8];
    __shared__ int   NT[5];

    if (tid < 5) {
        float a = 0.f, b = 0.f;
        for (int k = 0; k < 6; ++k) {
            a += Bm[(2 * tid) * 6 + k]     * theta[k];
            b += Bm[(2 * tid + 1) * 6 + k] * theta[k];
        }
        A[tid] = a; Bc[tid] = b;
        const int big = fabsf(a) > 1e-8f;
        BIGF[tid] = big;
        const float sa  = big ? a : 1.0f;
        const float sb  = (fabsf(b) > 1e-12f) ? b : 1e-12f;
        const float boa = b / sa;
        SBv[tid] = sb; BOA[tid] = boa;
        const float xl = tid / 5.0f, xr = (tid + 1) / 5.0f;
        {   // rightward traversal of this cell
            const float v = a * xl + b, den = xl + boa;
            const float sden = (fabsf(den) > 1e-12f) ? den : 1e-12f;
            const float ratio = (xr + boa) / sden;
            const float th = big ? logf(fmaxf(ratio, 1e-12f)) / sa : (xr - xl) / sb;
            const int valid = (fabsf(v) > 1e-12f) && (th >= 0.f) && (!big || ratio > 0.f);
            TAUR[tid] = valid ? th : 1e10f;
            LDRv[tid] = valid ? a * th : 0.f;
        }
        {   // leftward traversal
            const float v = a * xr + b, den = xr + boa;
            const float sden = (fabsf(den) > 1e-12f) ? den : 1e-12f;
            const float ratio = (xl + boa) / sden;
            const float th = big ? logf(fmaxf(ratio, 1e-12f)) / sa : (xl - xr) / sb;
            const int valid = (fabsf(v) > 1e-12f) && (th >= 0.f) && (!big || ratio > 0.f);
            TAUL[tid] = valid ? th : 1e10f;
            LDLv[tid] = valid ? a * th : 0.f;
        }
    }
    __syncthreads();
    if (tid < 12) {                      // cumulative chain tables per boundary
        const int j = tid % 6, dir = tid / 6;
        float tc = 0.f, lc = 0.f;
        if (dir == 0) {
            TR[j][0] = 0.f; LRm[j][0] = 0.f;
            for (int m = 1; m <= 5; ++m) {
                const int cell = j + m - 1;
                if (cell <= 4 && tc < 1e9f && TAUR[cell] < 1e9f) { tc += TAUR[cell]; lc += LDRv[cell]; }
                else tc = 1e10f;
                TR[j][m] = tc; LRm[j][m] = lc;
            }
        } else {
            TLm[j][0] = 0.f; LLm[j][0] = 0.f;
            for (int m = 1; m <= 5; ++m) {
                const int cell = j - m;
                if (cell >= 0 && tc < 1e9f && TAUL[cell] < 1e9f) { tc += TAUL[cell]; lc += LDLv[cell]; }
                else tc = 1e10f;
                TLm[j][m] = tc; LLm[j][m] = lc;
            }
        }
    }
    __syncthreads();
    if (tid < 5) {                       // per-cell thresholds
        const int c = tid;
        const float a = A[c], b = Bc[c], boa = BOA[c], sb = SBv[c];
        const int big = BIGF[c];
        const float xl = c / 5.0f, xr = (c + 1) / 5.0f;
        float cand[16]; int ncand = 0;
        if (big) {
            const float xs = -boa;       // direction switch v=0
            if (xs > xl && xs < xr) cand[ncand++] = xs;
        }
        for (int dir = 0; dir < 2; ++dir) {
            const int jb = (dir == 0) ? c + 1 : c;
            const float xb = jb / 5.0f;
            const float* Tc = (dir == 0) ? TR[jb] : TLm[jb];
            for (int m = 0; m <= 5; ++m) {
                const float th = (m == 0) ? 1.0f : (1.0f - Tc[m]);
                if (!(th > 0.f && th <= 1.0f)) continue;
                const float xt = big ? (xb + boa) * expf(-a * th) - boa
                                     : xb - sb * th;
                if (xt > xl && xt < xr) {
                    const float v = a * xt + b;
                    const int r = (v >= 0.f);
                    if ((r && dir == 0) || (!r && dir == 1))
                        if (ncand < 16) cand[ncand++] = xt;
                }
            }
        }
        for (int i = 1; i < ncand; ++i) {
            float v = cand[i]; int j = i - 1;
            while (j >= 0 && cand[j] > v) { cand[j + 1] = cand[j]; --j; }
            cand[j + 1] = v;
        }
        int nt = 0;
        for (int i = 0; i < ncand && nt < 8; ++i)
            if (nt == 0 || cand[i] - THR[c][nt - 1] > 1e-9f) { THR[c][nt] = cand[i]; ++nt; }
        NT[c] = nt;
        for (int k = nt; k < 8; ++k) THR[c][k] = 1e30f;
    }
    __syncthreads();
    if (tid < 45) {                      // per-segment coefficients
        const int c = tid / 9, sgi = tid % 9;
        const int nt = NT[c];
        if (sgi <= nt) {
            const float xl = c / 5.0f, xr = (c + 1) / 5.0f;
            const float lo = (sgi == 0) ? xl : THR[c][sgi - 1];
            const float hi = (sgi == nt) ? xr : THR[c][sgi];
            const float xm = 0.5f * (lo + hi);
            const float a = A[c], b = Bc[c], boa = BOA[c], sb = SBv[c];
            const int big = BIGF[c];
            float C0 = 0, FL = 0, G = 0, C1 = 0, C4 = 0, C2 = 0, D1 = 0, D2 = 0;
            const float v = a * xm + b;
            const float den = xm + boa;
            const float sden = (fabsf(den) > 1e-12f) ? den : 1e-12f;
            const int right = (v >= 0.f);
            const int jb = right ? c + 1 : c;
            const float xb = jb / 5.0f;
            const float ratio = (xb + boa) / sden;
            const float thit = big ? logf(fmaxf(ratio, 1e-12f)) / a : (xb - xm) / sb;
            const int valid = (fabsf(v) > 1e-12f) && (thit >= 0.f) && (!big || ratio > 0.f);
            if (!valid || thit >= 1.0f) {
                if (big) { const float ea = expf(a); C4 = ea; C2 = boa * (ea - 1.0f); }
                else     { C4 = 1.0f; C2 = b; }
                D2 = a;
            } else {
                const float s = 1.0f - thit;
                const float* Tc = right ? TR[jb] : TLm[jb];
                const float* Lc = right ? LRm[jb] : LLm[jb];
                int mm = 0;
                for (int m = 1; m <= 5; ++m) mm += (Tc[m] < s) ? 1 : 0;
                const float Lcum = Lc[mm], Tmm = Tc[mm];
                const int jb2 = right ? jb + mm : jb - mm;
                float P, Q;
                if (big) { FL = 1.0f; C0 = boa; P = logf(fabsf(xb + boa)) / a; Q = 1.0f / a; }
                else     { FL = 0.0f; C0 = 0.0f; P = xb / sb; Q = 1.0f / sb; }
                const float S0 = 1.0f - Tmm - P;        // srem = S0 + Q*u
                const int absorbed = right ? (jb2 == 5) : (jb2 == 0);
                if (absorbed) {
                    C2 = right ? 1.0f : 0.0f;
                    D1 = -a * Q; D2 = a * P + Lcum;
                } else {
                    const int cc = right ? jb2 : jb2 - 1;
                    const float x0 = jb2 / 5.0f;
                    const float a2 = A[cc], b2 = Bc[cc];
                    if (fabsf(a2) > 1e-8f) {
                        const float boa2 = b2 / a2;
                        G = a2 * Q; C1 = (x0 + boa2) * expf(a2 * S0); C2 = -boa2;
                    } else {
                        C4 = b2 * Q; C2 = x0 + b2 * S0;
                    }
                    D1 = (a2 - a) * Q; D2 = a * P + Lcum + a2 * S0;
                }
            }
            d_cf[tid * 2]     = make_float4(C0, G, C1, C4);
            d_cf[tid * 2 + 1] = make_float4(C2, D1, D2, FL);
        }
    }
    __syncthreads();
    // Bin table: NB bins; each fully inside one cell.
    for (int bin = tid; bin < NB; bin += blockDim.x) {
        const int c = bin / BPC;
        const float x_lo = (float)bin / (float)NB;
        int base = 0;
        float t0 = 1e30f, t1 = 1e30f;
        for (int k = 0; k < 8; ++k) {
            const float t = THR[c][k];
            if (t < x_lo) ++base;
            else if (t0 >= 1e29f) t0 = t;
            else if (t1 >= 1e29f) t1 = t;
        }
        float4 e;
        e.x = t0; e.y = t1;
        e.z = __int_as_float(c * 9 + base);
        e.w = 0.f;
        d_bin[bin] = e;
    }
}

__device__ __forceinline__ void eval_point(float x, float& z, float& ld,
                                           const float4* __restrict__ s_bin,
                                           const float4* __restrict__ s_cf)
{
    x = fminf(fmaxf(x, EPSC), 1.0f - EPSC);
    const int bin = (int)(x * (float)NB);           // x < 1 so bin <= NB-1
    const float4 be = s_bin[bin];
    const int seg = __float_as_int(be.z) + (be.x < x ? 1 : 0) + (be.y < x ? 1 : 0);
    const float4 c1 = s_cf[seg * 2];                // {C0, G, C1, C4}
    const float4 c2 = s_cf[seg * 2 + 1];            // {C2, D1, D2, FL}
    const float u = (c2.w != 0.0f) ? __logf(fabsf(x + c1.x)) : x;
    const float e = __expf(c1.y * u);
    z  = fmaf(c1.z, e, fmaf(c1.w, u, c2.x));
    ld = fmaf(c2.y, u, c2.z);
}

__global__ void __launch_bounds__(256)
flowcpab_main(const float* __restrict__ x, float* __restrict__ out, int n)
{
    __shared__ float4 s_bin[NB];
    __shared__ float4 s_cf[NC * 9 * 2];
    const int tid = threadIdx.x;
    for (int i = tid; i < NB; i += blockDim.x)        s_bin[i] = d_bin[i];
    for (int i = tid; i < NC * 9 * 2; i += blockDim.x) s_cf[i] = d_cf[i];
    __syncthreads();

    const int stride = gridDim.x * blockDim.x;

    if ((n & 3) == 0) {
        const int n4 = n >> 2;
        const float4* __restrict__ x4 = (const float4*)x;
        float4* __restrict__ z4 = (float4*)out;
        float4* __restrict__ l4 = (float4*)(out + n);
        for (int i = blockIdx.x * blockDim.x + tid; i < n4; i += stride) {
            const float4 xv = x4[i];
            float4 zv, lv;
            eval_point(xv.x, zv.x, lv.x, s_bin, s_cf);
            eval_point(xv.y, zv.y, lv.y, s_bin, s_cf);
            eval_point(xv.z, zv.z, lv.z, s_bin, s_cf);
            eval_point(xv.w, zv.w, lv.w, s_bin, s_cf);
            z4[i] = zv;
            l4[i] = lv;
        }
    } else {
        for (int i = blockIdx.x * blockDim.x + tid; i < n; i += stride) {
            float zz, ll;
            eval_point(x[i], zz, ll, s_bin, s_cf);
            out[i] = zz;
            out[n + i] = ll;
        }
    }
}

extern "C" void kernel_launch(void* const* d_in, const int* in_sizes, int n_in,
                              void* d_out, int out_size)
{
    const float* x     = (const float*)d_in[0];
    const float* theta = (const float*)d_in[1];
    const float* Bm    = (const float*)d_in[2];
    float* out = (float*)d_out;
    const int n = in_sizes[0];

    setup_kernel<<<1, 256>>>(theta, Bm);

    const int threads = 256;
    int work = ((n & 3) == 0) ? (n >> 2) : n;
    int blocks = (work + threads - 1) / threads;
    const int cap = 2368;                 // 148 SMs * 16: two clean waves at 8 blocks/SM
    if (blocks > cap) blocks = cap;
    if (blocks < 1) blocks = 1;
    flowcpab_main<<<blocks, threads>>>(x, out, n);
}

// round 5
// speedup vs baseline: 4.5232x; 1.2517x over previous
#include <cuda_runtime.h>
#include <cuda_bf16.h>

// FlowCPAB: per-bin linear interpolation of the exact closed-form map.
// Each block rebuilds (cheaply, in shared) the per-cell CPAB algebra:
//   segments where  u = FL ? log|x+C0| : x,
//                   z = C1*exp(G*u) + C4*u + C2,   ld = D1*u + D2
// then tabulates z(x), ld(x) at 2561 nodes and stores per-bin {z0,dz,ld0,dld}.
// z is C1 (z' = e^ld continuous), ld is C0; NB is a multiple of 5 so cell
// boundaries land on bin edges. Bins containing an interior threshold (ld-kink)
// are flagged (dz=1e30) and evaluated with the exact closed form instead.
// Interp error ~ f''*h^2/8 ~ 2e-8*f'' << 1e-3 tolerance.

#define NC 5
#define EPSC 1e-7f
#define NB 2560              // 5 * 512 bins
#define FNB 2560.0f

__device__ __forceinline__ void exact_eval(float x, float& z, float& ld,
                                           const float* __restrict__ thr,
                                           const float4* __restrict__ cf)
{
    x = fminf(fmaxf(x, EPSC), 1.0f - EPSC);
    const int c = min(NC - 1, (int)(x * 5.0f));
    int mm = 0;
#pragma unroll
    for (int k = 0; k < 8; ++k) mm += (thr[c * 8 + k] < x) ? 1 : 0;
    const int seg = c * 9 + mm;
    const float4 c1 = cf[seg * 2];          // {C0, G, C1, C4}
    const float4 c2 = cf[seg * 2 + 1];      // {C2, D1, D2, FL}
    const float u = (c2.w != 0.0f) ? __logf(fabsf(x + c1.x)) : x;
    const float e = __expf(c1.y * u);
    z  = fmaf(c1.z, e, fmaf(c1.w, u, c2.x));
    ld = fmaf(c2.y, u, c2.z);
}

__global__ void __launch_bounds__(256)
flowcpab_fused(const float* __restrict__ xin,
               const float* __restrict__ theta,
               const float* __restrict__ Bm,
               float* __restrict__ out, int n)
{
    __shared__ float  s_thr[NC * 8];
    __shared__ float4 s_cf[NC * 9 * 2];
    __shared__ float4 s_bin[NB];
    // setup temporaries
    __shared__ float A[5], Bc[5], BOA[5], SBv[5];
    __shared__ int   BIGF[5];
    __shared__ float TAUR[5], TAUL[5], LDRv[5], LDLv[5];
    __shared__ float TR[6][6], TLm[6][6], LRm[6][6], LLm[6][6];
    __shared__ int   NT[5];

    const int tid = threadIdx.x;

    // ---- Phase A: per-cell (a,b) and traversal times ----
    if (tid < 5) {
        float a = 0.f, b = 0.f;
#pragma unroll
        for (int k = 0; k < 6; ++k) {
            a += Bm[(2 * tid) * 6 + k]     * theta[k];
            b += Bm[(2 * tid + 1) * 6 + k] * theta[k];
        }
        A[tid] = a; Bc[tid] = b;
        const int big = fabsf(a) > 1e-8f;
        BIGF[tid] = big;
        const float sa  = big ? a : 1.0f;
        const float sb  = (fabsf(b) > 1e-12f) ? b : 1e-12f;
        const float boa = b / sa;
        SBv[tid] = sb; BOA[tid] = boa;
        const float xl = tid / 5.0f, xr = (tid + 1) / 5.0f;
        {
            const float v = a * xl + b, den = xl + boa;
            const float sden = (fabsf(den) > 1e-12f) ? den : 1e-12f;
            const float ratio = (xr + boa) / sden;
            const float th = big ? logf(fmaxf(ratio, 1e-12f)) / sa : (xr - xl) / sb;
            const int valid = (fabsf(v) > 1e-12f) && (th >= 0.f) && (!big || ratio > 0.f);
            TAUR[tid] = valid ? th : 1e10f;
            LDRv[tid] = valid ? a * th : 0.f;
        }
        {
            const float v = a * xr + b, den = xr + boa;
            const float sden = (fabsf(den) > 1e-12f) ? den : 1e-12f;
            const float ratio = (xl + boa) / sden;
            const float th = big ? logf(fmaxf(ratio, 1e-12f)) / sa : (xl - xr) / sb;
            const int valid = (fabsf(v) > 1e-12f) && (th >= 0.f) && (!big || ratio > 0.f);
            TAUL[tid] = valid ? th : 1e10f;
            LDLv[tid] = valid ? a * th : 0.f;
        }
    }
    __syncthreads();

    // ---- Phase B: cumulative chain tables per boundary ----
    if (tid < 12) {
        const int j = tid % 6, dir = tid / 6;
        float tc = 0.f, lc = 0.f;
        if (dir == 0) {
            TR[j][0] = 0.f; LRm[j][0] = 0.f;
            for (int m = 1; m <= 5; ++m) {
                const int cell = j + m - 1;
                if (cell <= 4 && tc < 1e9f && TAUR[cell] < 1e9f) { tc += TAUR[cell]; lc += LDRv[cell]; }
                else tc = 1e10f;
                TR[j][m] = tc; LRm[j][m] = lc;
            }
        } else {
            TLm[j][0] = 0.f; LLm[j][0] = 0.f;
            for (int m = 1; m <= 5; ++m) {
                const int cell = j - m;
                if (cell >= 0 && tc < 1e9f && TAUL[cell] < 1e9f) { tc += TAUL[cell]; lc += LDLv[cell]; }
                else tc = 1e10f;
                TLm[j][m] = tc; LLm[j][m] = lc;
            }
        }
    }
    __syncthreads();

    // ---- Phase C: per-cell thresholds ----
    if (tid < 5) {
        const int c = tid;
        const float a = A[c], b = Bc[c], boa = BOA[c], sb = SBv[c];
        const int big = BIGF[c];
        const float xl = c / 5.0f, xr = (c + 1) / 5.0f;
        float cand[16]; int ncand = 0;
        if (big) {
            const float xs = -boa;
            if (xs > xl && xs < xr) cand[ncand++] = xs;
        }
        for (int dir = 0; dir < 2; ++dir) {
            const int jb = (dir == 0) ? c + 1 : c;
            const float xb = jb / 5.0f;
            const float* Tc = (dir == 0) ? TR[jb] : TLm[jb];
            for (int m = 0; m <= 5; ++m) {
                const float th = (m == 0) ? 1.0f : (1.0f - Tc[m]);
                if (!(th > 0.f && th <= 1.0f)) continue;
                const float xt = big ? (xb + boa) * expf(-a * th) - boa
                                     : xb - sb * th;
                if (xt > xl && xt < xr) {
                    const float v = a * xt + b;
                    const int r = (v >= 0.f);
                    if ((r && dir == 0) || (!r && dir == 1))
                        if (ncand < 16) cand[ncand++] = xt;
                }
            }
        }
        for (int i = 1; i < ncand; ++i) {
            float v = cand[i]; int j = i - 1;
            while (j >= 0 && cand[j] > v) { cand[j + 1] = cand[j]; --j; }
            cand[j + 1] = v;
        }
        int nt = 0;
        float last = -1.f;
        for (int i = 0; i < ncand && nt < 8; ++i)
            if (nt == 0 || cand[i] - last > 1e-9f) { last = cand[i]; s_thr[c * 8 + nt] = last; ++nt; }
        NT[c] = nt;
        for (int k = nt; k < 8; ++k) s_thr[c * 8 + k] = 1e30f;
    }
    __syncthreads();

    // ---- Phase D: per-segment coefficients ----
    if (tid < 45) {
        const int c = tid / 9, sgi = tid % 9;
        const int nt = NT[c];
        float C0 = 0, FL = 0, G = 0, C1 = 0, C4 = 0, C2 = 0, D1 = 0, D2 = 0;
        if (sgi <= nt) {
            const float xl = c / 5.0f, xr = (c + 1) / 5.0f;
            const float lo = (sgi == 0) ? xl : s_thr[c * 8 + sgi - 1];
            const float hi = (sgi == nt) ? xr : s_thr[c * 8 + sgi];
            const float xm = 0.5f * (lo + hi);
            const float a = A[c], b = Bc[c], boa = BOA[c], sb = SBv[c];
            const int big = BIGF[c];
            const float v = a * xm + b;
            const float den = xm + boa;
            const float sden = (fabsf(den) > 1e-12f) ? den : 1e-12f;
            const int right = (v >= 0.f);
            const int jb = right ? c + 1 : c;
            const float xb = jb / 5.0f;
            const float ratio = (xb + boa) / sden;
            const float thit = big ? logf(fmaxf(ratio, 1e-12f)) / a : (xb - xm) / sb;
            const int valid = (fabsf(v) > 1e-12f) && (thit >= 0.f) && (!big || ratio > 0.f);
            if (!valid || thit >= 1.0f) {
                if (big) { const float ea = expf(a); C4 = ea; C2 = boa * (ea - 1.0f); }
                else     { C4 = 1.0f; C2 = b; }
                D2 = a;
            } else {
                const float s = 1.0f - thit;
                const float* Tc = right ? TR[jb] : TLm[jb];
                const float* Lc = right ? LRm[jb] : LLm[jb];
                int mm = 0;
                for (int m = 1; m <= 5; ++m) mm += (Tc[m] < s) ? 1 : 0;
                const float Lcum = Lc[mm], Tmm = Tc[mm];
                const int jb2 = right ? jb + mm : jb - mm;
                float P, Q;
                if (big) { FL = 1.0f; C0 = boa; P = logf(fabsf(xb + boa)) / a; Q = 1.0f / a; }
                else     { FL = 0.0f; C0 = 0.0f; P = xb / sb; Q = 1.0f / sb; }
                const float S0 = 1.0f - Tmm - P;
                const int absorbed = right ? (jb2 == 5) : (jb2 == 0);
                if (absorbed) {
                    C2 = right ? 1.0f : 0.0f;
                    D1 = -a * Q; D2 = a * P + Lcum;
                } else {
                    const int cc = right ? jb2 : jb2 - 1;
                    const float x0 = jb2 / 5.0f;
                    const float a2 = A[cc], b2 = Bc[cc];
                    if (fabsf(a2) > 1e-8f) {
                        const float boa2 = b2 / a2;
                        G = a2 * Q; C1 = (x0 + boa2) * expf(a2 * S0); C2 = -boa2;
                    } else {
                        C4 = b2 * Q; C2 = x0 + b2 * S0;
                    }
                    D1 = (a2 - a) * Q; D2 = a * P + Lcum + a2 * S0;
                }
            }
        }
        s_cf[tid * 2]     = make_float4(C0, G, C1, C4);
        s_cf[tid * 2 + 1] = make_float4(C2, D1, D2, FL);
    }
    __syncthreads();

    // ---- Phase E: build bin table (each bin: eval both end nodes exactly) ----
    for (int j = tid; j < NB; j += blockDim.x) {
        const float x0 = (float)j / FNB;
        const float x1 = (float)(j + 1) / FNB;
        float z0, l0, z1, l1;
        exact_eval(x0, z0, l0, s_thr, s_cf);
        exact_eval(x1, z1, l1, s_thr, s_cf);
        // mixed bin = any threshold strictly inside (x0, x1)
        const int c = j / (NB / 5);
        bool mixed = false;
#pragma unroll
        for (int k = 0; k < 8; ++k) {
            const float t = s_thr[c * 8 + k];
            mixed = mixed || (t > x0 && t < x1);
        }
        float4 e;
        e.x = z0;
        e.y = mixed ? 1e30f : (z1 - z0);
        e.z = l0;
        e.w = mixed ? 0.0f : (l1 - l0);
        s_bin[j] = e;
    }
    __syncthreads();

    // ---- Phase F: stream points ----
    const int stride = gridDim.x * blockDim.x;

    if ((n & 3) == 0) {
        const int n4 = n >> 2;
        const float4* __restrict__ x4 = (const float4*)xin;
        float4* __restrict__ z4 = (float4*)out;
        float4* __restrict__ l4 = (float4*)(out + n);
        for (int i = blockIdx.x * blockDim.x + tid; i < n4; i += stride) {
            const float4 xv = x4[i];
            float4 zv, lv;
            float xs[4] = {xv.x, xv.y, xv.z, xv.w};
            float zs[4], ls[4];
#pragma unroll
            for (int q = 0; q < 4; ++q) {
                float x = fminf(fmaxf(xs[q], EPSC), 1.0f - EPSC);
                const float xf = x * FNB;
                const int bin = (int)xf;
                const float fr = xf - (float)bin;
                const float4 nb = s_bin[bin];
                if (fabsf(nb.y) > 1e3f) {
                    exact_eval(x, zs[q], ls[q], s_thr, s_cf);
                } else {
                    zs[q] = fmaf(fr, nb.y, nb.x);
                    ls[q] = fmaf(fr, nb.w, nb.z);
                }
            }
            zv.x = zs[0]; zv.y = zs[1]; zv.z = zs[2]; zv.w = zs[3];
            lv.x = ls[0]; lv.y = ls[1]; lv.z = ls[2]; lv.w = ls[3];
            z4[i] = zv;
            l4[i] = lv;
        }
    } else {
        for (int i = blockIdx.x * blockDim.x + tid; i < n; i += stride) {
            float x = fminf(fmaxf(xin[i], EPSC), 1.0f - EPSC);
            const float xf = x * FNB;
            const int bin = (int)xf;
            const float fr = xf - (float)bin;
            const float4 nb = s_bin[bin];
            float z, ld;
            if (fabsf(nb.y) > 1e3f) exact_eval(x, z, ld, s_thr, s_cf);
            else { z = fmaf(fr, nb.y, nb.x); ld = fmaf(fr, nb.w, nb.z); }
            out[i] = z;
            out[n + i] = ld;
        }
    }
}

extern "C" void kernel_launch(void* const* d_in, const int* in_sizes, int n_in,
                              void* d_out, int out_size)
{
    const float* x     = (const float*)d_in[0];
    const float* theta = (const float*)d_in[1];
    const float* Bm    = (const float*)d_in[2];
    float* out = (float*)d_out;
    const int n = in_sizes[0];

    const int threads = 256;
    int blocks = 740;                    // 148 SMs * 5 resident blocks (42KB smem each)
    int work = ((n & 3) == 0) ? (n >> 2) : n;
    int maxb = (work + threads - 1) / threads;
    if (blocks > maxb) blocks = maxb;
    if (blocks < 1) blocks = 1;
    flowcpab_fused<<<blocks, threads>>>(x, theta, Bm, out, n);
}